// round 12
// baseline (speedup 1.0000x reference)
#include <cuda_runtime.h>
#include <cstdint>
#include <math.h>

#define Tt 64
#define NT 512
#define EPSF 1e-8f

__device__ __forceinline__ float sigmoidf_(float x) { return __fdividef(1.f, 1.f + __expf(-x)); }
__device__ __forceinline__ float softplusf_(float x) { return (x > 20.f) ? x : log1pf(expf(x)); }
__device__ __forceinline__ float ftanh(float x) {
    float e = __expf(fminf(fmaxf(2.f * x, -30.f), 30.f));
    return __fdividef(e - 1.f, e + 1.f);
}

__device__ __forceinline__ uint32_t s2u(const void* p) {
    uint32_t a;
    asm("{ .reg .u64 t; cvta.to.shared.u64 t, %1; cvt.u32.u64 %0, t; }" : "=r"(a) : "l"(p));
    return a;
}
__device__ __forceinline__ void st_peer(const void* lp, uint32_t peer, float v) {
    uint32_t la = s2u(lp), ra;
    asm("mapa.shared::cluster.u32 %0, %1, %2;" : "=r"(ra) : "r"(la), "r"(peer));
    asm volatile("st.shared::cluster.f32 [%0], %1;" :: "r"(ra), "f"(v));
}
// Arrive (release, cluster scope) on the PEER's mbarrier at the same smem offset.
__device__ __forceinline__ void arrive_peer(uint32_t local_mbar, uint32_t peer) {
    uint32_t ra;
    asm("mapa.shared::cluster.u32 %0, %1, %2;" : "=r"(ra) : "r"(local_mbar), "r"(peer));
    asm volatile("mbarrier.arrive.release.cluster.shared::cluster.b64 _, [%0];" :: "r"(ra) : "memory");
}
// Wait on local mbarrier, acquire at cluster scope.
__device__ __forceinline__ void mbar_wait(uint32_t mbar, uint32_t parity) {
    uint32_t done;
    asm volatile(
        "{\n\t.reg .pred p;\n\t"
        "mbarrier.try_wait.parity.acquire.cluster.shared::cta.b64 p, [%1], %2;\n\t"
        "selp.b32 %0, 1, 0, p;\n\t}"
        : "=r"(done) : "r"(mbar), "r"(parity) : "memory");
    if (!done) {
        asm volatile(
            "{\n\t.reg .pred P1;\n\t"
            "WL_%=:\n\t"
            "mbarrier.try_wait.parity.acquire.cluster.shared::cta.b64 P1, [%0], %1, 0x989680;\n\t"
            "@P1 bra.uni WD_%=;\n\t"
            "bra.uni WL_%=;\n\t"
            "WD_%=:\n\t}"
            :: "r"(mbar), "r"(parity) : "memory");
    }
}
#define MBAR_INIT(addr, cnt) \
    asm volatile("mbarrier.init.shared.b64 [%0], %1;" :: "r"(addr), "r"(cnt) : "memory")
#define CSYNC() do { \
    asm volatile("barrier.cluster.arrive.aligned;" ::: "memory"); \
    asm volatile("barrier.cluster.wait.aligned;" ::: "memory"); } while (0)

struct __align__(16) Smem {
    float Whs[128 * 272];
    float Wcs[64 * 128];
    float xc[Tt * 128];
    float scratchU[2448];
    float scratchF[1280];
    float chalf[128];
    float rv[64];
    float hl[272], hp[272];
    float fcl[64], fcp[2][64];
    float kw[64], kr[64], ev[64], av[64];
    float redA[32], redB[32];
    float red2[8], sc[16];
    float haloWp[2], haloWv[2], haloRp[2], haloRv[2];
    float rpart[64];
    float bws[200], brs[72], bfs[64], bcc[128];
    unsigned long long mbars[8];   // 5 used
};

__global__ __launch_bounds__(NT, 1) __cluster_dims__(2, 1, 1)
void ntm_kernel(const float* __restrict__ x,
                const float* __restrict__ Wc, const float* __restrict__ bc,
                const float* __restrict__ Wr, const float* __restrict__ br,
                const float* __restrict__ Ww, const float* __restrict__ bw,
                const float* __restrict__ Wf, const float* __restrict__ bf,
                const float* __restrict__ r_bias, const float* __restrict__ w_bias,
                const float* __restrict__ M_bias, float* __restrict__ out) {
    extern __shared__ float smem_raw[];
    Smem& s = *reinterpret_cast<Smem*>(smem_raw);
    const int tid = threadIdx.x;
    const int lane = tid & 31, wid = tid >> 5;
    uint32_t rank;
    asm("mov.u32 %0, %%cluster_ctarank;" : "=r"(rank));
    const uint32_t peer = rank ^ 1u;
    const int b = blockIdx.x >> 1;
    const float4* Wf4  = (const float4*)Wf;
    const float4* Wc4g = (const float4*)Wc;
    const float4* Wcs4 = (const float4*)s.Wcs;
    const float4* Whs4 = (const float4*)s.Whs;
    const uint32_t mb0 = s2u(&s.mbars[0]), mb1 = s2u(&s.mbars[1]),
                   mb2 = s2u(&s.mbars[2]), mb3 = s2u(&s.mbars[3]),
                   mb4 = s2u(&s.mbars[4]);

    float Mreg[64];
    float q, d;

    // ---- init ----
    if (tid == 0) {
        MBAR_INIT(mb0, 336);
        MBAR_INIT(mb1, 17);
        MBAR_INIT(mb2, 16);
        MBAR_INIT(mb3, 17);
        MBAR_INIT(mb4, 78);
    }
    for (int i = tid; i < 64 * 128; i += NT) {
        int j = i >> 7, c = i & 127;
        s.Wcs[i] = Wc[(size_t)(64 + j) * 256 + rank * 128 + c];
    }
    for (int i = tid; i < 128 * 272; i += NT) {
        int j = i / 272, col = i - j * 272;
        int gk = rank * 128 + j;
        float v = 0.f;
        if (col < 198) v = Ww[(size_t)gk * 198 + col];
        else if (col < 268) v = Wr[(size_t)gk * 70 + (col - 198)];
        s.Whs[i] = v;
    }
    for (int job = tid; job < Tt * 32; job += NT) {
        int tt = job >> 5, g4 = job & 31;
        const float* xrow = x + ((size_t)b * Tt + tt) * 64;
        float4 acc = make_float4(0.f, 0.f, 0.f, 0.f);
        #pragma unroll 16
        for (int j = 0; j < 64; ++j) {
            float v = xrow[j];
            float4 w4 = Wc4g[(size_t)j * 64 + rank * 32 + g4];
            acc.x = fmaf(v, w4.x, acc.x); acc.y = fmaf(v, w4.y, acc.y);
            acc.z = fmaf(v, w4.z, acc.z); acc.w = fmaf(v, w4.w, acc.w);
        }
        *(float4*)(s.xc + tt * 128 + 4 * g4) = acc;
    }
    {
        const int row = rank * 512 + tid;
        q = 0.f;
        const float* Mb = M_bias + (size_t)row * 64;
        #pragma unroll
        for (int j = 0; j < 64; ++j) { float v = Mb[j]; Mreg[j] = v; q += v * v; }
    }
    float wr = w_bias[rank * 512 + tid];
    if (tid < 64)  s.rv[tid] = r_bias[tid];
    if (tid < 198) s.bws[tid] = bw[tid];
    if (tid < 70)  s.brs[tid] = br[tid];
    if (tid < 64)  s.bfs[tid] = bf[tid];
    if (tid < 128) s.bcc[tid] = bc[rank * 128 + tid];
    __syncthreads();
    CSYNC();   // peers' mbarriers initialized before any arrive

    for (int t = 0; t < Tt; ++t) {
        const int par = t & 1;
        // ---- loop-top: ctrl r-GEMV + FC r-part(step t-1) ----
        if (tid < 256) {
            int g = tid & 31, sp = tid >> 5;
            float4 acc = make_float4(0.f, 0.f, 0.f, 0.f);
            #pragma unroll
            for (int j = 0; j < 8; ++j) {
                float v = s.rv[sp * 8 + j];
                float4 w4 = Wcs4[(size_t)(sp * 8 + j) * 32 + g];
                acc.x = fmaf(v, w4.x, acc.x); acc.y = fmaf(v, w4.y, acc.y);
                acc.z = fmaf(v, w4.z, acc.z); acc.w = fmaf(v, w4.w, acc.w);
            }
            *(float4*)(s.scratchU + sp * 128 + 4 * g) = acc;
        } else if (tid < 320) {
            int ft = tid - 256, gf = ft & 7, spf = ft >> 3;
            float4 acc = make_float4(0.f, 0.f, 0.f, 0.f);
            #pragma unroll
            for (int j = 0; j < 8; ++j) {
                float v = s.rv[spf * 8 + j];
                float4 w4 = Wf4[(size_t)(256 + spf * 8 + j) * 16 + rank * 8 + gf];
                acc.x = fmaf(v, w4.x, acc.x); acc.y = fmaf(v, w4.y, acc.y);
                acc.z = fmaf(v, w4.z, acc.z); acc.w = fmaf(v, w4.w, acc.w);
            }
            *(float4*)(s.scratchF + 1024 + spf * 32 + 4 * gf) = acc;
        }
        __syncthreads();                                // T1
        if (tid < 128) {
            float acc = s.xc[t * 128 + tid] + s.bcc[tid];
            #pragma unroll
            for (int k = 0; k < 8; ++k) acc += s.scratchU[k * 128 + tid];
            s.chalf[tid] = ftanh(acc);
        } else if (tid < 160 && t > 0) {
            int lo = tid - 128, o = rank * 32 + lo;
            float acc = s.bfs[o] + s.fcl[o] + s.fcp[par ^ 1][o];
            #pragma unroll
            for (int k = 0; k < 8; ++k) acc += s.scratchF[1024 + k * 32 + lo];
            out[((size_t)b * Tt + (t - 1)) * 64 + o] = sigmoidf_(acc);
        }
        __syncthreads();                                // T2

        // ---- head GEMV partials + FC c-part ----
        {
            int g = tid % 68, sp = tid / 68;
            float4 acc = make_float4(0.f, 0.f, 0.f, 0.f);
            #pragma unroll
            for (int j = 0; j < 16; ++j) {
                float v = s.chalf[sp * 16 + j];
                float4 w4 = Whs4[(size_t)(sp * 16 + j) * 68 + g];
                acc.x = fmaf(v, w4.x, acc.x); acc.y = fmaf(v, w4.y, acc.y);
                acc.z = fmaf(v, w4.z, acc.z); acc.w = fmaf(v, w4.w, acc.w);
            }
            *(float4*)(s.scratchU + sp * 272 + 4 * g) = acc;
            if (tid < 64) {
                int g2 = 36 + (tid >> 1), h = tid & 1;
                float4 a2 = make_float4(0.f, 0.f, 0.f, 0.f);
                #pragma unroll
                for (int j = 0; j < 8; ++j) {
                    int c = 112 + h * 8 + j;
                    float v = s.chalf[c];
                    float4 w4 = Whs4[(size_t)c * 68 + g2];
                    a2.x = fmaf(v, w4.x, a2.x); a2.y = fmaf(v, w4.y, a2.y);
                    a2.z = fmaf(v, w4.z, a2.z); a2.w = fmaf(v, w4.w, a2.w);
                }
                *(float4*)(s.scratchU + (7 + h) * 272 + 4 * g2) = a2;
            } else if (tid < 320) {
                int ft = tid - 64, gf = ft & 15, spf = ft >> 4;
                float4 af = make_float4(0.f, 0.f, 0.f, 0.f);
                #pragma unroll
                for (int j = 0; j < 8; ++j) {
                    float v = s.chalf[spf * 8 + j];
                    float4 w4 = Wf4[(size_t)(rank * 128 + spf * 8 + j) * 16 + gf];
                    af.x = fmaf(v, w4.x, af.x); af.y = fmaf(v, w4.y, af.y);
                    af.z = fmaf(v, w4.z, af.z); af.w = fmaf(v, w4.w, af.w);
                }
                *(float4*)(s.scratchF + spf * 64 + 4 * gf) = af;
            }
        }
        __syncthreads();                                // S4
        if (tid < 272) {
            float acc = 0.f;
            #pragma unroll
            for (int k = 0; k < 8; ++k) acc += s.scratchU[k * 272 + tid];
            if (tid >= 144) acc += s.scratchU[8 * 272 + tid];
            s.hl[tid] = acc;
            st_peer(&s.hp[tid], peer, acc);
        } else if (tid < 336) {
            int ft = tid - 272;
            float acc = 0.f;
            #pragma unroll
            for (int k = 0; k < 16; ++k) acc += s.scratchF[k * 64 + ft];
            s.fcl[ft] = acc;
            st_peer(&s.fcp[par][ft], peer, acc);
        }
        if (tid < 336) arrive_peer(mb0, peer);
        __syncthreads();
        mbar_wait(mb0, par);                            // X1

        // ---- transforms ----
        {
            float hv = 0.f;
            if (tid < 268)
                hv = s.hl[tid] + s.hp[tid] + ((tid < 198) ? s.bws[tid] : s.brs[tid - 198]);
            float kv = 0.f;
            if (tid < 64 || (tid >= 198 && tid < 262)) kv = ftanh(hv);
            if (tid < 64) s.kw[tid] = kv;
            else if (tid < 70) {
                const unsigned m6 = 0x3Fu;
                float a0 = __shfl_sync(m6, hv, 2);
                float a1 = __shfl_sync(m6, hv, 3);
                float a2 = __shfl_sync(m6, hv, 4);
                if (lane == 0) s.sc[0] = softplusf_(hv);
                else if (lane == 1) s.sc[1] = sigmoidf_(hv);
                else if (lane == 5) s.sc[5] = 1.f + softplusf_(hv);
                else {
                    float m = fmaxf(a0, fmaxf(a1, a2));
                    float e0 = __expf(a0 - m), e1 = __expf(a1 - m), e2 = __expf(a2 - m);
                    float z = e0 + e1 + e2;
                    float mine = (lane == 2) ? e0 : (lane == 3) ? e1 : e2;
                    s.sc[2 + (lane - 2)] = __fdividef(mine, z);
                }
            }
            else if (tid < 134) s.ev[tid - 70] = sigmoidf_(hv);
            else if (tid < 198) s.av[tid - 134] = ftanh(hv);
            else if (tid < 262) s.kr[tid - 198] = kv;
            else if (tid < 268) {
                const unsigned m6 = 0xFC0u;
                float a0 = __shfl_sync(m6, hv, 8);
                float a1 = __shfl_sync(m6, hv, 9);
                float a2 = __shfl_sync(m6, hv, 10);
                if (lane == 6) s.sc[8] = softplusf_(hv);
                else if (lane == 7) s.sc[9] = sigmoidf_(hv);
                else if (lane == 11) s.sc[13] = 1.f + softplusf_(hv);
                else {
                    float m = fmaxf(a0, fmaxf(a1, a2));
                    float e0 = __expf(a0 - m), e1 = __expf(a1 - m), e2 = __expf(a2 - m);
                    float z = e0 + e1 + e2;
                    float mine = (lane == 8) ? e0 : (lane == 9) ? e1 : e2;
                    s.sc[10 + (lane - 8)] = __fdividef(mine, z);
                }
            }
            float qq = kv * kv;
            if (wid < 2 || (wid >= 6 && wid <= 8)) {
                #pragma unroll
                for (int o = 16; o; o >>= 1) qq += __shfl_xor_sync(0xffffffffu, qq, o);
                if (lane == 0) s.red2[wid < 2 ? wid : wid - 4] = qq;
            }
        }
        __syncthreads();                                // S5

        // ---- Pass A ----
        d = 0.f;
        #pragma unroll
        for (int j4 = 0; j4 < 16; ++j4) {
            float4 kk = *(const float4*)(s.kw + 4 * j4);
            d += Mreg[4*j4]*kk.x + Mreg[4*j4+1]*kk.y + Mreg[4*j4+2]*kk.z + Mreg[4*j4+3]*kk.w;
        }

        // ---- write-head addressing ----
        float w;
        {
            float knw = __fsqrt_rn(s.red2[0] + s.red2[1]);
            float beta = s.sc[0], gg = s.sc[1];
            float sh0 = s.sc[2], sh1 = s.sc[3], sh2 = s.sc[4], gamma = s.sc[5];
            float p = __expf(__fdividef(beta * d, __fsqrt_rn(q) * knw + EPSF));
            s.scratchU[tid] = p;
            s.scratchU[512 + tid] = wr;
            float pw = p;
            #pragma unroll
            for (int o = 16; o; o >>= 1) pw += __shfl_xor_sync(0xffffffffu, pw, o);
            if (lane == 0) { s.redA[wid] = pw; st_peer(&s.redA[16 + wid], peer, pw); }
            if (tid == 511) { st_peer(&s.haloWp[0], peer, p); st_peer(&s.haloWv[0], peer, wr); }
            if (tid == 0)   { st_peer(&s.haloWp[1], peer, p); st_peer(&s.haloWv[1], peer, wr); }
            if (lane == 0 || tid == 511) arrive_peer(mb1, peer);
            __syncthreads();
            mbar_wait(mb1, par);                        // X2
            float Z = 0.f;
            #pragma unroll
            for (int k = 0; k < 8; ++k) {
                float4 v4 = ((const float4*)s.redA)[k];
                Z += (v4.x + v4.y) + (v4.z + v4.w);
            }
            float invZ = __fdividef(1.f, Z);
            float pl = tid ? s.scratchU[tid - 1] : s.haloWp[0];
            float pr = (tid < 511) ? s.scratchU[tid + 1] : s.haloWp[1];
            float vl = tid ? s.scratchU[512 + tid - 1] : s.haloWv[0];
            float vr = (tid < 511) ? s.scratchU[512 + tid + 1] : s.haloWv[1];
            float ps = sh0 * pr + sh1 * p  + sh2 * pl;
            float vs = sh0 * vr + sh1 * wr + sh2 * vl;
            float ws = gg * invZ * ps + (1.f - gg) * vs;
            float wp = exp2f(gamma * __log2f(ws + EPSF));
            float sw = wp;
            #pragma unroll
            for (int o = 16; o; o >>= 1) sw += __shfl_xor_sync(0xffffffffu, sw, o);
            if (lane == 0) {
                s.redB[wid] = sw; st_peer(&s.redB[16 + wid], peer, sw);
                arrive_peer(mb2, peer);
            }
            __syncthreads();
            mbar_wait(mb2, par);                        // X3
            float S = 0.f;
            #pragma unroll
            for (int k = 0; k < 8; ++k) {
                float4 v4 = ((const float4*)s.redB)[k];
                S += (v4.x + v4.y) + (v4.z + v4.w);
            }
            w = wp * __fdividef(1.f, S);
        }

        // ---- Pass B (4 ops/element) ----
        {
            float nd = 0.f, nq = 0.f;
            #pragma unroll
            for (int j4 = 0; j4 < 16; ++j4) {
                float4 kk = *(const float4*)(s.kr + 4 * j4);
                float4 ee = *(const float4*)(s.ev + 4 * j4);
                float4 aa = *(const float4*)(s.av + 4 * j4);
                #pragma unroll
                for (int e = 0; e < 4; ++e) {
                    int j = 4 * j4 + e;
                    float ev_ = (e==0)?ee.x:(e==1)?ee.y:(e==2)?ee.z:ee.w;
                    float av_ = (e==0)?aa.x:(e==1)?aa.y:(e==2)?aa.z:aa.w;
                    float kv_ = (e==0)?kk.x:(e==1)?kk.y:(e==2)?kk.z:kk.w;
                    float mr = Mreg[j];
                    float u = fmaf(-mr, ev_, av_);
                    mr = fmaf(w, u, mr);
                    Mreg[j] = mr;
                    nd = fmaf(mr, kv_, nd); nq = fmaf(mr, mr, nq);
                }
            }
            d = nd; q = nq;
        }

        // ---- read-head addressing + merged final exchange ----
        {
            float knr = __fsqrt_rn(s.red2[2] + s.red2[3] + s.red2[4]);
            float beta = s.sc[8], gg = s.sc[9];
            float sh0 = s.sc[10], sh1 = s.sc[11], sh2 = s.sc[12], gamma = s.sc[13];
            float p = __expf(__fdividef(beta * d, __fsqrt_rn(q) * knr + EPSF));
            s.scratchU[tid] = p;
            s.scratchU[512 + tid] = w;
            float pw = p;
            #pragma unroll
            for (int o = 16; o; o >>= 1) pw += __shfl_xor_sync(0xffffffffu, pw, o);
            if (lane == 0) { s.redA[wid] = pw; st_peer(&s.redA[16 + wid], peer, pw); }
            if (tid == 511) { st_peer(&s.haloRp[0], peer, p); st_peer(&s.haloRv[0], peer, w); }
            if (tid == 0)   { st_peer(&s.haloRp[1], peer, p); st_peer(&s.haloRv[1], peer, w); }
            if (lane == 0 || tid == 511) arrive_peer(mb3, peer);
            __syncthreads();
            mbar_wait(mb3, par);                        // X4
            float Z = 0.f;
            #pragma unroll
            for (int k = 0; k < 8; ++k) {
                float4 v4 = ((const float4*)s.redA)[k];
                Z += (v4.x + v4.y) + (v4.z + v4.w);
            }
            float invZ = __fdividef(1.f, Z);
            float pl = tid ? s.scratchU[tid - 1] : s.haloRp[0];
            float pr = (tid < 511) ? s.scratchU[tid + 1] : s.haloRp[1];
            float vl = tid ? s.scratchU[512 + tid - 1] : s.haloRv[0];
            float vr = (tid < 511) ? s.scratchU[512 + tid + 1] : s.haloRv[1];
            float ps = sh0 * pr + sh1 * p + sh2 * pl;
            float vs = sh0 * vr + sh1 * w + sh2 * vl;
            float ws = gg * invZ * ps + (1.f - gg) * vs;
            float wp = exp2f(gamma * __log2f(ws + EPSF));
            float sw = wp;
            #pragma unroll
            for (int o = 16; o; o >>= 1) sw += __shfl_xor_sync(0xffffffffu, sw, o);
            if (lane == 0) {
                s.redB[wid] = sw; st_peer(&s.redB[16 + wid], peer, sw);
                if (tid >= 64) arrive_peer(mb4, peer);
            }

            // unnormalized butterfly with wp
            {
                float A[32];
                bool up = (lane & 16);
                #pragma unroll
                for (int i = 0; i < 32; ++i) {
                    float lo = wp * Mreg[i];
                    float hi = wp * Mreg[i + 32];
                    float keep = up ? hi : lo;
                    float send = up ? lo : hi;
                    A[i] = keep + __shfl_xor_sync(0xffffffffu, send, 16);
                }
                #pragma unroll
                for (int o = 8; o >= 1; o >>= 1) {
                    int hl2 = o << 1;
                    bool u2 = (lane & o);
                    #pragma unroll
                    for (int i = 0; i < 16; ++i) {
                        if (i < hl2) {
                            float keep = u2 ? A[i + hl2] : A[i];
                            float send = u2 ? A[i] : A[i + hl2];
                            A[i] = keep + __shfl_xor_sync(0xffffffffu, send, o);
                        }
                    }
                }
                s.scratchU[1024 + wid * 64 + 2 * lane]     = A[0];
                s.scratchU[1024 + wid * 64 + 2 * lane + 1] = A[1];
            }
            __syncthreads();                            // S8
            float rlu = 0.f;
            if (tid < 64) {
                #pragma unroll
                for (int k = 0; k < 16; ++k) rlu += s.scratchU[1024 + k * 64 + tid];
                st_peer(&s.rpart[tid], peer, rlu);
                arrive_peer(mb4, peer);
            }
            mbar_wait(mb4, par);                        // X5
            float S = 0.f;
            #pragma unroll
            for (int k = 0; k < 8; ++k) {
                float4 v4 = ((const float4*)s.redB)[k];
                S += (v4.x + v4.y) + (v4.z + v4.w);
            }
            float invS = __fdividef(1.f, S);
            wr = wp * invS;
            if (tid < 64) s.rv[tid] = (rlu + s.rpart[tid]) * invS;
        }
        __syncthreads();                                // S9
    }

    // ---- epilogue: output t = 63 ----
    if (tid < 64) {
        int gf = tid & 7, spf = tid >> 3;
        float4 acc = make_float4(0.f, 0.f, 0.f, 0.f);
        #pragma unroll
        for (int j = 0; j < 8; ++j) {
            float v = s.rv[spf * 8 + j];
            float4 w4 = Wf4[(size_t)(256 + spf * 8 + j) * 16 + rank * 8 + gf];
            acc.x = fmaf(v, w4.x, acc.x); acc.y = fmaf(v, w4.y, acc.y);
            acc.z = fmaf(v, w4.z, acc.z); acc.w = fmaf(v, w4.w, acc.w);
        }
        *(float4*)(s.scratchF + 1024 + spf * 32 + 4 * gf) = acc;
    }
    __syncthreads();
    if (tid < 32) {
        int o = rank * 32 + tid;
        float acc = s.bfs[o] + s.fcl[o] + s.fcp[1][o];
        #pragma unroll
        for (int k = 0; k < 8; ++k) acc += s.scratchF[1024 + k * 32 + tid];
        out[((size_t)b * Tt + 63) * 64 + o] = sigmoidf_(acc);
    }
    CSYNC();   // no CTA exits while peer may still push
}

extern "C" void kernel_launch(void* const* d_in, const int* in_sizes, int n_in,
                              void* d_out, int out_size) {
    (void)in_sizes; (void)n_in; (void)out_size;
    cudaFuncSetAttribute(ntm_kernel, cudaFuncAttributeMaxDynamicSharedMemorySize,
                         (int)sizeof(Smem));
    ntm_kernel<<<128, NT, sizeof(Smem)>>>(
        (const float*)d_in[0],   // x
        (const float*)d_in[1],   // Wc
        (const float*)d_in[2],   // bc
        (const float*)d_in[3],   // Wr
        (const float*)d_in[4],   // br
        (const float*)d_in[5],   // Ww
        (const float*)d_in[6],   // bw
        (const float*)d_in[7],   // Wf
        (const float*)d_in[8],   // bf
        (const float*)d_in[9],   // r_bias
        (const float*)d_in[10],  // w_bias
        (const float*)d_in[11],  // M_bias
        (float*)d_out);
}

// round 15
// speedup vs baseline: 1.0080x; 1.0080x over previous
#include <cuda_runtime.h>
#include <cstdint>
#include <math.h>

#define Tt 64
#define NT 512
#define EPSF 1e-8f

typedef unsigned long long ull;

__device__ __forceinline__ float sigmoidf_(float x) { return __fdividef(1.f, 1.f + __expf(-x)); }
__device__ __forceinline__ float softplusf_(float x) { return (x > 20.f) ? x : log1pf(expf(x)); }
__device__ __forceinline__ float ftanh(float x) {
    float e = __expf(fminf(fmaxf(2.f * x, -30.f), 30.f));
    return __fdividef(e - 1.f, e + 1.f);
}

__device__ __forceinline__ ull pack2(float x, float y) {
    ull r; asm("mov.b64 %0, {%1, %2};" : "=l"(r) : "f"(x), "f"(y)); return r;
}
__device__ __forceinline__ void unpack2(ull v, float& x, float& y) {
    asm("mov.b64 {%0, %1}, %2;" : "=f"(x), "=f"(y) : "l"(v));
}
__device__ __forceinline__ ull fma2(ull a, ull b, ull c) {
    ull r; asm("fma.rn.f32x2 %0, %1, %2, %3;" : "=l"(r) : "l"(a), "l"(b), "l"(c)); return r;
}
__device__ __forceinline__ ull mul2(ull a, ull b) {
    ull r; asm("mul.rn.f32x2 %0, %1, %2;" : "=l"(r) : "l"(a), "l"(b)); return r;
}
__device__ __forceinline__ ull add2(ull a, ull b) {
    ull r; asm("add.rn.f32x2 %0, %1, %2;" : "=l"(r) : "l"(a), "l"(b)); return r;
}

__device__ __forceinline__ uint32_t s2u(const void* p) {
    uint32_t a;
    asm("{ .reg .u64 t; cvta.to.shared.u64 t, %1; cvt.u32.u64 %0, t; }" : "=r"(a) : "l"(p));
    return a;
}
__device__ __forceinline__ void st_peer(const void* lp, uint32_t peer, float v) {
    uint32_t la = s2u(lp), ra;
    asm("mapa.shared::cluster.u32 %0, %1, %2;" : "=r"(ra) : "r"(la), "r"(peer));
    asm volatile("st.shared::cluster.f32 [%0], %1;" :: "r"(ra), "f"(v));
}
__device__ __forceinline__ void st_peer64(const void* lp, uint32_t peer, ull v) {
    uint32_t la = s2u(lp), ra;
    asm("mapa.shared::cluster.u32 %0, %1, %2;" : "=r"(ra) : "r"(la), "r"(peer));
    asm volatile("st.shared::cluster.b64 [%0], %1;" :: "r"(ra), "l"(v));
}
#define CSYNC() do { \
    asm volatile("barrier.cluster.arrive.aligned;" ::: "memory"); \
    asm volatile("barrier.cluster.wait.aligned;" ::: "memory"); } while (0)

struct __align__(16) Smem {
    float Whs[128 * 272];
    float Wcs[64 * 128];
    float xc[Tt * 128];
    float scratchU[2448];
    float scratchF[1280];
    float chalf[128];
    float rv[64];
    float hl[272], hp[272];
    float fcl[64], fcp[2][64];
    float kw[64], kr[64], ev[64], av[64];
    float redA[32], redB[32];
    float red2[8], sc[16];
    float haloWp[2], haloWv[2], haloRp[2], haloRv[2];
    float rpart[64];
    float bws[200], brs[72], bfs[64], bcc[128];
};

__global__ __launch_bounds__(NT, 1) __cluster_dims__(2, 1, 1)
void ntm_kernel(const float* __restrict__ x,
                const float* __restrict__ Wc, const float* __restrict__ bc,
                const float* __restrict__ Wr, const float* __restrict__ br,
                const float* __restrict__ Ww, const float* __restrict__ bw,
                const float* __restrict__ Wf, const float* __restrict__ bf,
                const float* __restrict__ r_bias, const float* __restrict__ w_bias,
                const float* __restrict__ M_bias, float* __restrict__ out) {
    extern __shared__ float smem_raw[];
    Smem& s = *reinterpret_cast<Smem*>(smem_raw);
    const int tid = threadIdx.x;
    const int lane = tid & 31, wid = tid >> 5;
    uint32_t rank;
    asm("mov.u32 %0, %%cluster_ctarank;" : "=r"(rank));
    const uint32_t peer = rank ^ 1u;
    const int b = blockIdx.x >> 1;
    const float4* Wf4  = (const float4*)Wf;
    const float4* Wc4g = (const float4*)Wc;
    const float4* Wcs4 = (const float4*)s.Wcs;
    const float4* Whs4 = (const float4*)s.Whs;

    ull Mreg2[32];           // M row, packed f32x2
    float q, d;

    // ---- init ----
    for (int i = tid; i < 64 * 128; i += NT) {
        int j = i >> 7, c = i & 127;
        s.Wcs[i] = Wc[(size_t)(64 + j) * 256 + rank * 128 + c];
    }
    for (int i = tid; i < 128 * 272; i += NT) {
        int j = i / 272, col = i - j * 272;
        int gk = rank * 128 + j;
        float v = 0.f;
        if (col < 198) v = Ww[(size_t)gk * 198 + col];
        else if (col < 268) v = Wr[(size_t)gk * 70 + (col - 198)];
        s.Whs[i] = v;
    }
    for (int job = tid; job < Tt * 32; job += NT) {
        int tt = job >> 5, g4 = job & 31;
        const float* xrow = x + ((size_t)b * Tt + tt) * 64;
        float4 acc = make_float4(0.f, 0.f, 0.f, 0.f);
        #pragma unroll 16
        for (int j = 0; j < 64; ++j) {
            float v = xrow[j];
            float4 w4 = Wc4g[(size_t)j * 64 + rank * 32 + g4];
            acc.x = fmaf(v, w4.x, acc.x); acc.y = fmaf(v, w4.y, acc.y);
            acc.z = fmaf(v, w4.z, acc.z); acc.w = fmaf(v, w4.w, acc.w);
        }
        *(float4*)(s.xc + tt * 128 + 4 * g4) = acc;
    }
    {
        const int row = rank * 512 + tid;
        const ull* Mb2 = (const ull*)(M_bias + (size_t)row * 64);
        ull q2 = 0;
        #pragma unroll
        for (int j = 0; j < 32; ++j) { Mreg2[j] = Mb2[j]; q2 = fma2(Mreg2[j], Mreg2[j], q2); }
        float qx, qy; unpack2(q2, qx, qy);
        q = qx + qy;
    }
    float wr = w_bias[rank * 512 + tid];
    if (tid < 64)  s.rv[tid] = r_bias[tid];
    if (tid < 198) s.bws[tid] = bw[tid];
    if (tid < 70)  s.brs[tid] = br[tid];
    if (tid < 64)  s.bfs[tid] = bf[tid];
    if (tid < 128) s.bcc[tid] = bc[rank * 128 + tid];
    __syncthreads();
    CSYNC();

    for (int t = 0; t < Tt; ++t) {
        const int par = t & 1;
        // ---- loop-top: ctrl r-GEMV + FC r-part(step t-1) ----
        if (tid < 256) {
            int g = tid & 31, sp = tid >> 5;
            float4 acc = make_float4(0.f, 0.f, 0.f, 0.f);
            #pragma unroll
            for (int j = 0; j < 8; ++j) {
                float v = s.rv[sp * 8 + j];
                float4 w4 = Wcs4[(size_t)(sp * 8 + j) * 32 + g];
                acc.x = fmaf(v, w4.x, acc.x); acc.y = fmaf(v, w4.y, acc.y);
                acc.z = fmaf(v, w4.z, acc.z); acc.w = fmaf(v, w4.w, acc.w);
            }
            *(float4*)(s.scratchU + sp * 128 + 4 * g) = acc;
        } else if (tid < 320) {
            int ft = tid - 256, gf = ft & 7, spf = ft >> 3;
            float4 acc = make_float4(0.f, 0.f, 0.f, 0.f);
            #pragma unroll
            for (int j = 0; j < 8; ++j) {
                float v = s.rv[spf * 8 + j];
                float4 w4 = Wf4[(size_t)(256 + spf * 8 + j) * 16 + rank * 8 + gf];
                acc.x = fmaf(v, w4.x, acc.x); acc.y = fmaf(v, w4.y, acc.y);
                acc.z = fmaf(v, w4.z, acc.z); acc.w = fmaf(v, w4.w, acc.w);
            }
            *(float4*)(s.scratchF + 1024 + spf * 32 + 4 * gf) = acc;
        }
        __syncthreads();                                // T1
        if (tid < 128) {
            float acc = s.xc[t * 128 + tid] + s.bcc[tid];
            #pragma unroll
            for (int k = 0; k < 8; ++k) acc += s.scratchU[k * 128 + tid];
            s.chalf[tid] = ftanh(acc);
        } else if (tid < 160 && t > 0) {
            int lo = tid - 128, o = rank * 32 + lo;
            float acc = s.bfs[o] + s.fcl[o] + s.fcp[par ^ 1][o];
            #pragma unroll
            for (int k = 0; k < 8; ++k) acc += s.scratchF[1024 + k * 32 + lo];
            out[((size_t)b * Tt + (t - 1)) * 64 + o] = sigmoidf_(acc);
        }
        __syncthreads();                                // T2

        // ---- head GEMV partials + FC c-part ----
        {
            int g = tid % 68, sp = tid / 68;
            float4 acc = make_float4(0.f, 0.f, 0.f, 0.f);
            #pragma unroll
            for (int j = 0; j < 16; ++j) {
                float v = s.chalf[sp * 16 + j];
                float4 w4 = Whs4[(size_t)(sp * 16 + j) * 68 + g];
                acc.x = fmaf(v, w4.x, acc.x); acc.y = fmaf(v, w4.y, acc.y);
                acc.z = fmaf(v, w4.z, acc.z); acc.w = fmaf(v, w4.w, acc.w);
            }
            *(float4*)(s.scratchU + sp * 272 + 4 * g) = acc;
            if (tid < 64) {
                int g2 = 36 + (tid >> 1), h = tid & 1;
                float4 a2 = make_float4(0.f, 0.f, 0.f, 0.f);
                #pragma unroll
                for (int j = 0; j < 8; ++j) {
                    int c = 112 + h * 8 + j;
                    float v = s.chalf[c];
                    float4 w4 = Whs4[(size_t)c * 68 + g2];
                    a2.x = fmaf(v, w4.x, a2.x); a2.y = fmaf(v, w4.y, a2.y);
                    a2.z = fmaf(v, w4.z, a2.z); a2.w = fmaf(v, w4.w, a2.w);
                }
                *(float4*)(s.scratchU + (7 + h) * 272 + 4 * g2) = a2;
            } else if (tid < 320) {
                int ft = tid - 64, gf = ft & 15, spf = ft >> 4;
                float4 af = make_float4(0.f, 0.f, 0.f, 0.f);
                #pragma unroll
                for (int j = 0; j < 8; ++j) {
                    float v = s.chalf[spf * 8 + j];
                    float4 w4 = Wf4[(size_t)(rank * 128 + spf * 8 + j) * 16 + gf];
                    af.x = fmaf(v, w4.x, af.x); af.y = fmaf(v, w4.y, af.y);
                    af.z = fmaf(v, w4.z, af.z); af.w = fmaf(v, w4.w, af.w);
                }
                *(float4*)(s.scratchF + spf * 64 + 4 * gf) = af;
            }
        }
        __syncthreads();                                // S4
        if (tid < 272) {
            float acc = 0.f;
            #pragma unroll
            for (int k = 0; k < 8; ++k) acc += s.scratchU[k * 272 + tid];
            if (tid >= 144) acc += s.scratchU[8 * 272 + tid];
            s.hl[tid] = acc;
            st_peer(&s.hp[tid], peer, acc);
        } else if (tid < 336) {
            int ft = tid - 272;
            float acc = 0.f;
            #pragma unroll
            for (int k = 0; k < 16; ++k) acc += s.scratchF[k * 64 + ft];
            s.fcl[ft] = acc;
            st_peer(&s.fcp[par][ft], peer, acc);
        }
        CSYNC();                                        // C1

        // ---- transforms ----
        {
            float hv = 0.f;
            if (tid < 268)
                hv = s.hl[tid] + s.hp[tid] + ((tid < 198) ? s.bws[tid] : s.brs[tid - 198]);
            float kv = 0.f;
            if (tid < 64 || (tid >= 198 && tid < 262)) kv = ftanh(hv);
            if (tid < 64) s.kw[tid] = kv;
            else if (tid < 70) {
                const unsigned m6 = 0x3Fu;
                float a0 = __shfl_sync(m6, hv, 2);
                float a1 = __shfl_sync(m6, hv, 3);
                float a2 = __shfl_sync(m6, hv, 4);
                if (lane == 0) s.sc[0] = softplusf_(hv);
                else if (lane == 1) s.sc[1] = sigmoidf_(hv);
                else if (lane == 5) s.sc[5] = 1.f + softplusf_(hv);
                else {
                    float m = fmaxf(a0, fmaxf(a1, a2));
                    float e0 = __expf(a0 - m), e1 = __expf(a1 - m), e2 = __expf(a2 - m);
                    float z = e0 + e1 + e2;
                    float mine = (lane == 2) ? e0 : (lane == 3) ? e1 : e2;
                    s.sc[2 + (lane - 2)] = __fdividef(mine, z);
                }
            }
            else if (tid < 134) s.ev[tid - 70] = sigmoidf_(hv);
            else if (tid < 198) s.av[tid - 134] = ftanh(hv);
            else if (tid < 262) s.kr[tid - 198] = kv;
            else if (tid < 268) {
                const unsigned m6 = 0xFC0u;
                float a0 = __shfl_sync(m6, hv, 8);
                float a1 = __shfl_sync(m6, hv, 9);
                float a2 = __shfl_sync(m6, hv, 10);
                if (lane == 6) s.sc[8] = softplusf_(hv);
                else if (lane == 7) s.sc[9] = sigmoidf_(hv);
                else if (lane == 11) s.sc[13] = 1.f + softplusf_(hv);
                else {
                    float m = fmaxf(a0, fmaxf(a1, a2));
                    float e0 = __expf(a0 - m), e1 = __expf(a1 - m), e2 = __expf(a2 - m);
                    float z = e0 + e1 + e2;
                    float mine = (lane == 8) ? e0 : (lane == 9) ? e1 : e2;
                    s.sc[10 + (lane - 8)] = __fdividef(mine, z);
                }
            }
            float qq = kv * kv;
            if (wid < 2 || (wid >= 6 && wid <= 8)) {
                #pragma unroll
                for (int o = 16; o; o >>= 1) qq += __shfl_xor_sync(0xffffffffu, qq, o);
                if (lane == 0) s.red2[wid < 2 ? wid : wid - 4] = qq;
            }
        }
        __syncthreads();                                // S5

        // ---- Pass A: packed dot(M, kw) ----
        {
            const ull* kw2 = (const ull*)s.kw;
            ull d2 = 0;
            #pragma unroll
            for (int j = 0; j < 32; ++j) d2 = fma2(Mreg2[j], kw2[j], d2);
            float dx, dy; unpack2(d2, dx, dy);
            d = dx + dy;
        }

        // ---- write-head addressing ----
        float w;
        {
            float knw = __fsqrt_rn(s.red2[0] + s.red2[1]);
            float beta = s.sc[0], gg = s.sc[1];
            float sh0 = s.sc[2], sh1 = s.sc[3], sh2 = s.sc[4], gamma = s.sc[5];
            float p = __expf(__fdividef(beta * d, __fsqrt_rn(q) * knw + EPSF));
            s.scratchU[tid] = p;
            s.scratchU[512 + tid] = wr;
            float pw = p;
            #pragma unroll
            for (int o = 16; o; o >>= 1) pw += __shfl_xor_sync(0xffffffffu, pw, o);
            if (lane == 0) { s.redA[wid] = pw; st_peer(&s.redA[16 + wid], peer, pw); }
            if (tid == 511) { st_peer(&s.haloWp[0], peer, p); st_peer(&s.haloWv[0], peer, wr); }
            if (tid == 0)   { st_peer(&s.haloWp[1], peer, p); st_peer(&s.haloWv[1], peer, wr); }
            CSYNC();                                    // C2
            float Z = 0.f;
            #pragma unroll
            for (int k = 0; k < 8; ++k) {
                float4 v4 = ((const float4*)s.redA)[k];
                Z += (v4.x + v4.y) + (v4.z + v4.w);
            }
            float invZ = __fdividef(1.f, Z);
            float pl = tid ? s.scratchU[tid - 1] : s.haloWp[0];
            float pr = (tid < 511) ? s.scratchU[tid + 1] : s.haloWp[1];
            float vl = tid ? s.scratchU[512 + tid - 1] : s.haloWv[0];
            float vr = (tid < 511) ? s.scratchU[512 + tid + 1] : s.haloWv[1];
            float ps = sh0 * pr + sh1 * p  + sh2 * pl;
            float vs = sh0 * vr + sh1 * wr + sh2 * vl;
            float ws = gg * invZ * ps + (1.f - gg) * vs;
            float wp = exp2f(gamma * __log2f(ws + EPSF));
            float sw = wp;
            #pragma unroll
            for (int o = 16; o; o >>= 1) sw += __shfl_xor_sync(0xffffffffu, sw, o);
            if (lane == 0) { s.redB[wid] = sw; st_peer(&s.redB[16 + wid], peer, sw); }
            CSYNC();                                    // C3
            float S = 0.f;
            #pragma unroll
            for (int k = 0; k < 8; ++k) {
                float4 v4 = ((const float4*)s.redB)[k];
                S += (v4.x + v4.y) + (v4.z + v4.w);
            }
            w = wp * __fdividef(1.f, S);
        }

        // ---- Pass B: packed erase/add + dot + sumsq ----
        {
            const ull* kr2 = (const ull*)s.kr;
            const ull* ev2 = (const ull*)s.ev;
            const ull* av2 = (const ull*)s.av;
            const ull W2 = pack2(w, w);
            const ull NEG1 = pack2(-1.f, -1.f);
            ull d2 = 0, q2 = 0;
            #pragma unroll
            for (int j = 0; j < 32; ++j) {
                ull me = mul2(Mreg2[j], ev2[j]);
                ull u  = fma2(me, NEG1, av2[j]);    // a - m*e
                ull m2 = fma2(W2, u, Mreg2[j]);     // m + w*u
                Mreg2[j] = m2;
                d2 = fma2(m2, kr2[j], d2);
                q2 = fma2(m2, m2, q2);
            }
            float dx, dy, qx, qy;
            unpack2(d2, dx, dy); unpack2(q2, qx, qy);
            d = dx + dy; q = qx + qy;
        }

        // ---- read-head addressing + merged final exchange ----
        {
            float knr = __fsqrt_rn(s.red2[2] + s.red2[3] + s.red2[4]);
            float beta = s.sc[8], gg = s.sc[9];
            float sh0 = s.sc[10], sh1 = s.sc[11], sh2 = s.sc[12], gamma = s.sc[13];
            float p = __expf(__fdividef(beta * d, __fsqrt_rn(q) * knr + EPSF));
            s.scratchU[tid] = p;
            s.scratchU[512 + tid] = w;
            float pw = p;
            #pragma unroll
            for (int o = 16; o; o >>= 1) pw += __shfl_xor_sync(0xffffffffu, pw, o);
            if (lane == 0) { s.redA[wid] = pw; st_peer(&s.redA[16 + wid], peer, pw); }
            if (tid == 511) { st_peer(&s.haloRp[0], peer, p); st_peer(&s.haloRv[0], peer, w); }
            if (tid == 0)   { st_peer(&s.haloRp[1], peer, p); st_peer(&s.haloRv[1], peer, w); }
            CSYNC();                                    // C4
            float Z = 0.f;
            #pragma unroll
            for (int k = 0; k < 8; ++k) {
                float4 v4 = ((const float4*)s.redA)[k];
                Z += (v4.x + v4.y) + (v4.z + v4.w);
            }
            float invZ = __fdividef(1.f, Z);
            float pl = tid ? s.scratchU[tid - 1] : s.haloRp[0];
            float pr = (tid < 511) ? s.scratchU[tid + 1] : s.haloRp[1];
            float vl = tid ? s.scratchU[512 + tid - 1] : s.haloRv[0];
            float vr = (tid < 511) ? s.scratchU[512 + tid + 1] : s.haloRv[1];
            float ps = sh0 * pr + sh1 * p + sh2 * pl;
            float vs = sh0 * vr + sh1 * w + sh2 * vl;
            float ws = gg * invZ * ps + (1.f - gg) * vs;
            float wp = exp2f(gamma * __log2f(ws + EPSF));
            float sw = wp;
            #pragma unroll
            for (int o = 16; o; o >>= 1) sw += __shfl_xor_sync(0xffffffffu, sw, o);
            if (lane == 0) { s.redB[wid] = sw; st_peer(&s.redB[16 + wid], peer, sw); }

            // packed unnormalized butterfly with wp
            ull rlocal = 0;
            {
                const ull WP2 = pack2(wp, wp);
                ull A[16];
                bool up = (lane & 16);
                #pragma unroll
                for (int i = 0; i < 16; ++i) {
                    ull lo = mul2(WP2, Mreg2[i]);
                    ull hi = mul2(WP2, Mreg2[i + 16]);
                    ull keep = up ? hi : lo;
                    ull send = up ? lo : hi;
                    A[i] = add2(keep, __shfl_xor_sync(0xffffffffu, send, 16));
                }
                #pragma unroll
                for (int o = 8; o >= 1; o >>= 1) {
                    bool u2 = (lane & o);
                    #pragma unroll
                    for (int i = 0; i < 8; ++i) {
                        if (i < o) {
                            ull keep = u2 ? A[i + o] : A[i];
                            ull send = u2 ? A[i] : A[i + o];
                            A[i] = add2(keep, __shfl_xor_sync(0xffffffffu, send, o));
                        }
                    }
                }
                // lane holds elements (2*lane, 2*lane+1) packed
                *(ull*)(s.scratchU + 1024 + wid * 64 + 2 * lane) = A[0];
            }
            __syncthreads();                            // S8
            if (tid < 32) {
                #pragma unroll
                for (int k = 0; k < 16; ++k)
                    rlocal = add2(rlocal, *(const ull*)(s.scratchU + 1024 + k * 64 + 2 * tid));
                st_peer64(&s.rpart[2 * tid], peer, rlocal);
            }
            CSYNC();                                    // C5 (S partials + r partials)
            float S = 0.f;
            #pragma unroll
            for (int k = 0; k < 8; ++k) {
                float4 v4 = ((const float4*)s.redB)[k];
                S += (v4.x + v4.y) + (v4.z + v4.w);
            }
            float invS = __fdividef(1.f, S);
            wr = wp * invS;
            if (tid < 32) {
                ull rp = *(const ull*)(s.rpart + 2 * tid);
                ull rvv = mul2(add2(rlocal, rp), pack2(invS, invS));
                *(ull*)(s.rv + 2 * tid) = rvv;
            }
        }
        __syncthreads();                                // S9
    }

    // ---- epilogue: output t = 63 ----
    if (tid < 64) {
        int gf = tid & 7, spf = tid >> 3;
        float4 acc = make_float4(0.f, 0.f, 0.f, 0.f);
        #pragma unroll
        for (int j = 0; j < 8; ++j) {
            float v = s.rv[spf * 8 + j];
            float4 w4 = Wf4[(size_t)(256 + spf * 8 + j) * 16 + rank * 8 + gf];
            acc.x = fmaf(v, w4.x, acc.x); acc.y = fmaf(v, w4.y, acc.y);
            acc.z = fmaf(v, w4.z, acc.z); acc.w = fmaf(v, w4.w, acc.w);
        }
        *(float4*)(s.scratchF + 1024 + spf * 32 + 4 * gf) = acc;
    }
    __syncthreads();
    if (tid < 32) {
        int o = rank * 32 + tid;
        float acc = s.bfs[o] + s.fcl[o] + s.fcp[1][o];
        #pragma unroll
        for (int k = 0; k < 8; ++k) acc += s.scratchF[1024 + k * 32 + tid];
        out[((size_t)b * Tt + 63) * 64 + o] = sigmoidf_(acc);
    }
    CSYNC();
}

extern "C" void kernel_launch(void* const* d_in, const int* in_sizes, int n_in,
                              void* d_out, int out_size) {
    (void)in_sizes; (void)n_in; (void)out_size;
    cudaFuncSetAttribute(ntm_kernel, cudaFuncAttributeMaxDynamicSharedMemorySize,
                         (int)sizeof(Smem));
    ntm_kernel<<<128, NT, sizeof(Smem)>>>(
        (const float*)d_in[0],   // x
        (const float*)d_in[1],   // Wc
        (const float*)d_in[2],   // bc
        (const float*)d_in[3],   // Wr
        (const float*)d_in[4],   // br
        (const float*)d_in[5],   // Ww
        (const float*)d_in[6],   // bw
        (const float*)d_in[7],   // Wf
        (const float*)d_in[8],   // bf
        (const float*)d_in[9],   // r_bias
        (const float*)d_in[10],  // w_bias
        (const float*)d_in[11],  // M_bias
        (float*)d_out);
}

// round 17
// speedup vs baseline: 1.0097x; 1.0017x over previous
#include <cuda_runtime.h>
#include <cstdint>
#include <math.h>

#define Tt 64
#define NT 512
#define EPSF 1e-8f

__device__ __forceinline__ float sigmoidf_(float x) { return __fdividef(1.f, 1.f + __expf(-x)); }
__device__ __forceinline__ float softplusf_(float x) { return (x > 20.f) ? x : log1pf(expf(x)); }
__device__ __forceinline__ float ftanh(float x) {
    float e = __expf(fminf(fmaxf(2.f * x, -30.f), 30.f));
    return __fdividef(e - 1.f, e + 1.f);
}

__device__ __forceinline__ uint32_t s2u(const void* p) {
    uint32_t a;
    asm("{ .reg .u64 t; cvta.to.shared.u64 t, %1; cvt.u32.u64 %0, t; }" : "=r"(a) : "l"(p));
    return a;
}
__device__ __forceinline__ void st_peer(const void* lp, uint32_t peer, float v) {
    uint32_t la = s2u(lp), ra;
    asm("mapa.shared::cluster.u32 %0, %1, %2;" : "=r"(ra) : "r"(la), "r"(peer));
    asm volatile("st.shared::cluster.f32 [%0], %1;" :: "r"(ra), "f"(v));
}
__device__ __forceinline__ void arrive_peer(uint32_t local_mbar, uint32_t peer) {
    uint32_t ra;
    asm("mapa.shared::cluster.u32 %0, %1, %2;" : "=r"(ra) : "r"(local_mbar), "r"(peer));
    asm volatile("mbarrier.arrive.release.cluster.shared::cluster.b64 _, [%0];" :: "r"(ra) : "memory");
}
__device__ __forceinline__ void mbar_wait(uint32_t mbar, uint32_t parity) {
    uint32_t done;
    asm volatile(
        "{\n\t.reg .pred p;\n\t"
        "mbarrier.try_wait.parity.acquire.cluster.shared::cta.b64 p, [%1], %2;\n\t"
        "selp.b32 %0, 1, 0, p;\n\t}"
        : "=r"(done) : "r"(mbar), "r"(parity) : "memory");
    if (!done) {
        asm volatile(
            "{\n\t.reg .pred P1;\n\t"
            "WL_%=:\n\t"
            "mbarrier.try_wait.parity.acquire.cluster.shared::cta.b64 P1, [%0], %1, 0x989680;\n\t"
            "@P1 bra.uni WD_%=;\n\t"
            "bra.uni WL_%=;\n\t"
            "WD_%=:\n\t}"
            :: "r"(mbar), "r"(parity) : "memory");
    }
}
#define MBAR_INIT(addr, cnt) \
    asm volatile("mbarrier.init.shared.b64 [%0], %1;" :: "r"(addr), "r"(cnt) : "memory")
#define CSYNC() do { \
    asm volatile("barrier.cluster.arrive.aligned;" ::: "memory"); \
    asm volatile("barrier.cluster.wait.aligned;" ::: "memory"); } while (0)

struct __align__(16) Smem {
    float Whs[128 * 272];
    float Wcs[64 * 128];
    float xc[Tt * 128];
    float scratchU[2448];
    float scratchF[1280];
    float chalf[128];
    float rv[64];
    float hl[272], hp[272];
    float fcl[64], fcp[2][64];
    float kw[64], kr[64], ev[64], av[64];
    float redA[32], redB[32];
    float red2[8], sc[16];
    float haloWp[2], haloWv[2], haloRp[2], haloRv[2];
    float rpart[64];
    float bws[200], brs[72], bfs[64], bcc[128];
    unsigned long long mbars[4];    // C2..C5
};

__global__ __launch_bounds__(NT, 1) __cluster_dims__(2, 1, 1)
void ntm_kernel(const float* __restrict__ x,
                const float* __restrict__ Wc, const float* __restrict__ bc,
                const float* __restrict__ Wr, const float* __restrict__ br,
                const float* __restrict__ Ww, const float* __restrict__ bw,
                const float* __restrict__ Wf, const float* __restrict__ bf,
                const float* __restrict__ r_bias, const float* __restrict__ w_bias,
                const float* __restrict__ M_bias, float* __restrict__ out) {
    extern __shared__ float smem_raw[];
    Smem& s = *reinterpret_cast<Smem*>(smem_raw);
    const int tid = threadIdx.x;
    const int lane = tid & 31, wid = tid >> 5;
    uint32_t rank;
    asm("mov.u32 %0, %%cluster_ctarank;" : "=r"(rank));
    const uint32_t peer = rank ^ 1u;
    const int b = blockIdx.x >> 1;
    const float4* Wf4  = (const float4*)Wf;
    const float4* Wc4g = (const float4*)Wc;
    const float4* Wcs4 = (const float4*)s.Wcs;
    const float4* Whs4 = (const float4*)s.Whs;
    const uint32_t mbC2 = s2u(&s.mbars[0]), mbC3 = s2u(&s.mbars[1]),
                   mbC4 = s2u(&s.mbars[2]), mbC5 = s2u(&s.mbars[3]);

    float Mreg[64];
    float q, d;

    // ---- init ----
    if (tid == 0) {
        MBAR_INIT(mbC2, 17);    // 16 lane0 + tid511
        MBAR_INIT(mbC3, 16);    // 16 lane0
        MBAR_INIT(mbC4, 17);    // 16 lane0 + tid511
        MBAR_INIT(mbC5, 80);    // 16 lane0 + 64 r-pushers
    }
    for (int i = tid; i < 64 * 128; i += NT) {
        int j = i >> 7, c = i & 127;
        s.Wcs[i] = Wc[(size_t)(64 + j) * 256 + rank * 128 + c];
    }
    for (int i = tid; i < 128 * 272; i += NT) {
        int j = i / 272, col = i - j * 272;
        int gk = rank * 128 + j;
        float v = 0.f;
        if (col < 198) v = Ww[(size_t)gk * 198 + col];
        else if (col < 268) v = Wr[(size_t)gk * 70 + (col - 198)];
        s.Whs[i] = v;
    }
    for (int job = tid; job < Tt * 32; job += NT) {
        int tt = job >> 5, g4 = job & 31;
        const float* xrow = x + ((size_t)b * Tt + tt) * 64;
        float4 acc = make_float4(0.f, 0.f, 0.f, 0.f);
        #pragma unroll 16
        for (int j = 0; j < 64; ++j) {
            float v = xrow[j];
            float4 w4 = Wc4g[(size_t)j * 64 + rank * 32 + g4];
            acc.x = fmaf(v, w4.x, acc.x); acc.y = fmaf(v, w4.y, acc.y);
            acc.z = fmaf(v, w4.z, acc.z); acc.w = fmaf(v, w4.w, acc.w);
        }
        *(float4*)(s.xc + tt * 128 + 4 * g4) = acc;
    }
    {
        const int row = rank * 512 + tid;
        q = 0.f;
        const float* Mb = M_bias + (size_t)row * 64;
        #pragma unroll
        for (int j = 0; j < 64; ++j) { float v = Mb[j]; Mreg[j] = v; q += v * v; }
    }
    float wr = w_bias[rank * 512 + tid];
    if (tid < 64)  s.rv[tid] = r_bias[tid];
    if (tid < 198) s.bws[tid] = bw[tid];
    if (tid < 70)  s.brs[tid] = br[tid];
    if (tid < 64)  s.bfs[tid] = bf[tid];
    if (tid < 128) s.bcc[tid] = bc[rank * 128 + tid];
    __syncthreads();
    CSYNC();   // peers' mbarriers initialized before any arrive

    for (int t = 0; t < Tt; ++t) {
        const int par = t & 1;
        // ---- loop-top: ctrl r-GEMV + FC r-part(step t-1) ----
        if (tid < 256) {
            int g = tid & 31, sp = tid >> 5;
            float4 acc = make_float4(0.f, 0.f, 0.f, 0.f);
            #pragma unroll
            for (int j = 0; j < 8; ++j) {
                float v = s.rv[sp * 8 + j];
                float4 w4 = Wcs4[(size_t)(sp * 8 + j) * 32 + g];
                acc.x = fmaf(v, w4.x, acc.x); acc.y = fmaf(v, w4.y, acc.y);
                acc.z = fmaf(v, w4.z, acc.z); acc.w = fmaf(v, w4.w, acc.w);
            }
            *(float4*)(s.scratchU + sp * 128 + 4 * g) = acc;
        } else if (tid < 320) {
            int ft = tid - 256, gf = ft & 7, spf = ft >> 3;
            float4 acc = make_float4(0.f, 0.f, 0.f, 0.f);
            #pragma unroll
            for (int j = 0; j < 8; ++j) {
                float v = s.rv[spf * 8 + j];
                float4 w4 = Wf4[(size_t)(256 + spf * 8 + j) * 16 + rank * 8 + gf];
                acc.x = fmaf(v, w4.x, acc.x); acc.y = fmaf(v, w4.y, acc.y);
                acc.z = fmaf(v, w4.z, acc.z); acc.w = fmaf(v, w4.w, acc.w);
            }
            *(float4*)(s.scratchF + 1024 + spf * 32 + 4 * gf) = acc;
        }
        __syncthreads();                                // T1
        if (tid < 128) {
            float acc = s.xc[t * 128 + tid] + s.bcc[tid];
            #pragma unroll
            for (int k = 0; k < 8; ++k) acc += s.scratchU[k * 128 + tid];
            s.chalf[tid] = ftanh(acc);
        } else if (tid < 160 && t > 0) {
            int lo = tid - 128, o = rank * 32 + lo;
            float acc = s.bfs[o] + s.fcl[o] + s.fcp[par ^ 1][o];
            #pragma unroll
            for (int k = 0; k < 8; ++k) acc += s.scratchF[1024 + k * 32 + lo];
            out[((size_t)b * Tt + (t - 1)) * 64 + o] = sigmoidf_(acc);
        }
        __syncthreads();                                // T2

        // ---- head GEMV partials + FC c-part ----
        {
            int g = tid % 68, sp = tid / 68;
            float4 acc = make_float4(0.f, 0.f, 0.f, 0.f);
            #pragma unroll
            for (int j = 0; j < 16; ++j) {
                float v = s.chalf[sp * 16 + j];
                float4 w4 = Whs4[(size_t)(sp * 16 + j) * 68 + g];
                acc.x = fmaf(v, w4.x, acc.x); acc.y = fmaf(v, w4.y, acc.y);
                acc.z = fmaf(v, w4.z, acc.z); acc.w = fmaf(v, w4.w, acc.w);
            }
            *(float4*)(s.scratchU + sp * 272 + 4 * g) = acc;
            if (tid < 64) {
                int g2 = 36 + (tid >> 1), h = tid & 1;
                float4 a2 = make_float4(0.f, 0.f, 0.f, 0.f);
                #pragma unroll
                for (int j = 0; j < 8; ++j) {
                    int c = 112 + h * 8 + j;
                    float v = s.chalf[c];
                    float4 w4 = Whs4[(size_t)c * 68 + g2];
                    a2.x = fmaf(v, w4.x, a2.x); a2.y = fmaf(v, w4.y, a2.y);
                    a2.z = fmaf(v, w4.z, a2.z); a2.w = fmaf(v, w4.w, a2.w);
                }
                *(float4*)(s.scratchU + (7 + h) * 272 + 4 * g2) = a2;
            } else if (tid < 320) {
                int ft = tid - 64, gf = ft & 15, spf = ft >> 4;
                float4 af = make_float4(0.f, 0.f, 0.f, 0.f);
                #pragma unroll
                for (int j = 0; j < 8; ++j) {
                    float v = s.chalf[spf * 8 + j];
                    float4 w4 = Wf4[(size_t)(rank * 128 + spf * 8 + j) * 16 + gf];
                    af.x = fmaf(v, w4.x, af.x); af.y = fmaf(v, w4.y, af.y);
                    af.z = fmaf(v, w4.z, af.z); af.w = fmaf(v, w4.w, af.w);
                }
                *(float4*)(s.scratchF + spf * 64 + 4 * gf) = af;
            }
        }
        __syncthreads();                                // S4
        if (tid < 272) {
            float acc = 0.f;
            #pragma unroll
            for (int k = 0; k < 8; ++k) acc += s.scratchU[k * 272 + tid];
            if (tid >= 144) acc += s.scratchU[8 * 272 + tid];
            s.hl[tid] = acc;
            st_peer(&s.hp[tid], peer, acc);
        } else if (tid < 336) {
            int ft = tid - 272;
            float acc = 0.f;
            #pragma unroll
            for (int k = 0; k < 16; ++k) acc += s.scratchF[k * 64 + ft];
            s.fcl[ft] = acc;
            st_peer(&s.fcp[par][ft], peer, acc);
        }
        CSYNC();                                        // C1 (bulk: HW cluster barrier)

        // ---- transforms ----
        {
            float hv = 0.f;
            if (tid < 268)
                hv = s.hl[tid] + s.hp[tid] + ((tid < 198) ? s.bws[tid] : s.brs[tid - 198]);
            float kv = 0.f;
            if (tid < 64 || (tid >= 198 && tid < 262)) kv = ftanh(hv);
            if (tid < 64) s.kw[tid] = kv;
            else if (tid < 70) {
                const unsigned m6 = 0x3Fu;
                float a0 = __shfl_sync(m6, hv, 2);
                float a1 = __shfl_sync(m6, hv, 3);
                float a2 = __shfl_sync(m6, hv, 4);
                if (lane == 0) s.sc[0] = softplusf_(hv);
                else if (lane == 1) s.sc[1] = sigmoidf_(hv);
                else if (lane == 5) s.sc[5] = 1.f + softplusf_(hv);
                else {
                    float m = fmaxf(a0, fmaxf(a1, a2));
                    float e0 = __expf(a0 - m), e1 = __expf(a1 - m), e2 = __expf(a2 - m);
                    float z = e0 + e1 + e2;
                    float mine = (lane == 2) ? e0 : (lane == 3) ? e1 : e2;
                    s.sc[2 + (lane - 2)] = __fdividef(mine, z);
                }
            }
            else if (tid < 134) s.ev[tid - 70] = sigmoidf_(hv);
            else if (tid < 198) s.av[tid - 134] = ftanh(hv);
            else if (tid < 262) s.kr[tid - 198] = kv;
            else if (tid < 268) {
                const unsigned m6 = 0xFC0u;
                float a0 = __shfl_sync(m6, hv, 8);
                float a1 = __shfl_sync(m6, hv, 9);
                float a2 = __shfl_sync(m6, hv, 10);
                if (lane == 6) s.sc[8] = softplusf_(hv);
                else if (lane == 7) s.sc[9] = sigmoidf_(hv);
                else if (lane == 11) s.sc[13] = 1.f + softplusf_(hv);
                else {
                    float m = fmaxf(a0, fmaxf(a1, a2));
                    float e0 = __expf(a0 - m), e1 = __expf(a1 - m), e2 = __expf(a2 - m);
                    float z = e0 + e1 + e2;
                    float mine = (lane == 8) ? e0 : (lane == 9) ? e1 : e2;
                    s.sc[10 + (lane - 8)] = __fdividef(mine, z);
                }
            }
            float qq = kv * kv;
            if (wid < 2 || (wid >= 6 && wid <= 8)) {
                #pragma unroll
                for (int o = 16; o; o >>= 1) qq += __shfl_xor_sync(0xffffffffu, qq, o);
                if (lane == 0) s.red2[wid < 2 ? wid : wid - 4] = qq;
            }
        }
        __syncthreads();                                // S5

        // ---- Pass A ----
        d = 0.f;
        #pragma unroll
        for (int j4 = 0; j4 < 16; ++j4) {
            float4 kk = *(const float4*)(s.kw + 4 * j4);
            d += Mreg[4*j4]*kk.x + Mreg[4*j4+1]*kk.y + Mreg[4*j4+2]*kk.z + Mreg[4*j4+3]*kk.w;
        }

        // ---- write-head addressing ----
        float w;
        {
            float knw = __fsqrt_rn(s.red2[0] + s.red2[1]);
            float beta = s.sc[0], gg = s.sc[1];
            float sh0 = s.sc[2], sh1 = s.sc[3], sh2 = s.sc[4], gamma = s.sc[5];
            float p = __expf(__fdividef(beta * d, __fsqrt_rn(q) * knw + EPSF));
            s.scratchU[tid] = p;
            s.scratchU[512 + tid] = wr;
            float pw = p;
            #pragma unroll
            for (int o = 16; o; o >>= 1) pw += __shfl_xor_sync(0xffffffffu, pw, o);
            if (lane == 0) { s.redA[wid] = pw; st_peer(&s.redA[16 + wid], peer, pw); }
            if (tid == 511) { st_peer(&s.haloWp[0], peer, p); st_peer(&s.haloWv[0], peer, wr); }
            if (tid == 0)   { st_peer(&s.haloWp[1], peer, p); st_peer(&s.haloWv[1], peer, wr); }
            if (lane == 0 || tid == 511) arrive_peer(mbC2, peer);
            __syncthreads();                            // local ordering of scratchU/redA
            mbar_wait(mbC2, par);                       // C2
            float Z = 0.f;
            #pragma unroll
            for (int k = 0; k < 8; ++k) {
                float4 v4 = ((const float4*)s.redA)[k];
                Z += (v4.x + v4.y) + (v4.z + v4.w);
            }
            float invZ = __fdividef(1.f, Z);
            float pl = tid ? s.scratchU[tid - 1] : s.haloWp[0];
            float pr = (tid < 511) ? s.scratchU[tid + 1] : s.haloWp[1];
            float vl = tid ? s.scratchU[512 + tid - 1] : s.haloWv[0];
            float vr = (tid < 511) ? s.scratchU[512 + tid + 1] : s.haloWv[1];
            float ps = sh0 * pr + sh1 * p  + sh2 * pl;
            float vs = sh0 * vr + sh1 * wr + sh2 * vl;
            float ws = gg * invZ * ps + (1.f - gg) * vs;
            float wp = exp2f(gamma * __log2f(ws + EPSF));
            float sw = wp;
            #pragma unroll
            for (int o = 16; o; o >>= 1) sw += __shfl_xor_sync(0xffffffffu, sw, o);
            if (lane == 0) {
                s.redB[wid] = sw; st_peer(&s.redB[16 + wid], peer, sw);
                arrive_peer(mbC3, peer);
            }
            __syncthreads();
            mbar_wait(mbC3, par);                       // C3
            float S = 0.f;
            #pragma unroll
            for (int k = 0; k < 8; ++k) {
                float4 v4 = ((const float4*)s.redB)[k];
                S += (v4.x + v4.y) + (v4.z + v4.w);
            }
            w = wp * __fdividef(1.f, S);
        }

        // ---- Pass B (4 ops/element) ----
        {
            float nd = 0.f, nq = 0.f;
            #pragma unroll
            for (int j4 = 0; j4 < 16; ++j4) {
                float4 kk = *(const float4*)(s.kr + 4 * j4);
                float4 ee = *(const float4*)(s.ev + 4 * j4);
                float4 aa = *(const float4*)(s.av + 4 * j4);
                #pragma unroll
                for (int e = 0; e < 4; ++e) {
                    int j = 4 * j4 + e;
                    float ev_ = (e==0)?ee.x:(e==1)?ee.y:(e==2)?ee.z:ee.w;
                    float av_ = (e==0)?aa.x:(e==1)?aa.y:(e==2)?aa.z:aa.w;
                    float kv_ = (e==0)?kk.x:(e==1)?kk.y:(e==2)?kk.z:kk.w;
                    float mr = Mreg[j];
                    float u = fmaf(-mr, ev_, av_);
                    mr = fmaf(w, u, mr);
                    Mreg[j] = mr;
                    nd = fmaf(mr, kv_, nd); nq = fmaf(mr, mr, nq);
                }
            }
            d = nd; q = nq;
        }

        // ---- read-head addressing + merged final exchange ----
        {
            float knr = __fsqrt_rn(s.red2[2] + s.red2[3] + s.red2[4]);
            float beta = s.sc[8], gg = s.sc[9];
            float sh0 = s.sc[10], sh1 = s.sc[11], sh2 = s.sc[12], gamma = s.sc[13];
            float p = __expf(__fdividef(beta * d, __fsqrt_rn(q) * knr + EPSF));
            s.scratchU[tid] = p;
            s.scratchU[512 + tid] = w;
            float pw = p;
            #pragma unroll
            for (int o = 16; o; o >>= 1) pw += __shfl_xor_sync(0xffffffffu, pw, o);
            if (lane == 0) { s.redA[wid] = pw; st_peer(&s.redA[16 + wid], peer, pw); }
            if (tid == 511) { st_peer(&s.haloRp[0], peer, p); st_peer(&s.haloRv[0], peer, w); }
            if (tid == 0)   { st_peer(&s.haloRp[1], peer, p); st_peer(&s.haloRv[1], peer, w); }
            if (lane == 0 || tid == 511) arrive_peer(mbC4, peer);
            __syncthreads();
            mbar_wait(mbC4, par);                       // C4
            float Z = 0.f;
            #pragma unroll
            for (int k = 0; k < 8; ++k) {
                float4 v4 = ((const float4*)s.redA)[k];
                Z += (v4.x + v4.y) + (v4.z + v4.w);
            }
            float invZ = __fdividef(1.f, Z);
            float pl = tid ? s.scratchU[tid - 1] : s.haloRp[0];
            float pr = (tid < 511) ? s.scratchU[tid + 1] : s.haloRp[1];
            float vl = tid ? s.scratchU[512 + tid - 1] : s.haloRv[0];
            float vr = (tid < 511) ? s.scratchU[512 + tid + 1] : s.haloRv[1];
            float ps = sh0 * pr + sh1 * p + sh2 * pl;
            float vs = sh0 * vr + sh1 * w + sh2 * vl;
            float ws = gg * invZ * ps + (1.f - gg) * vs;
            float wp = exp2f(gamma * __log2f(ws + EPSF));
            float sw = wp;
            #pragma unroll
            for (int o = 16; o; o >>= 1) sw += __shfl_xor_sync(0xffffffffu, sw, o);
            if (lane == 0) {
                s.redB[wid] = sw; st_peer(&s.redB[16 + wid], peer, sw);
                arrive_peer(mbC5, peer);
            }

            // unnormalized butterfly with wp
            {
                float A[32];
                bool up = (lane & 16);
                #pragma unroll
                for (int i = 0; i < 32; ++i) {
                    float lo = wp * Mreg[i];
                    float hi = wp * Mreg[i + 32];
                    float keep = up ? hi : lo;
                    float send = up ? lo : hi;
                    A[i] = keep + __shfl_xor_sync(0xffffffffu, send, 16);
                }
                #pragma unroll
                for (int o = 8; o >= 1; o >>= 1) {
                    int hl2 = o << 1;
                    bool u2 = (lane & o);
                    #pragma unroll
                    for (int i = 0; i < 16; ++i) {
                        if (i < hl2) {
                            float keep = u2 ? A[i + hl2] : A[i];
                            float send = u2 ? A[i] : A[i + hl2];
                            A[i] = keep + __shfl_xor_sync(0xffffffffu, send, o);
                        }
                    }
                }
                s.scratchU[1024 + wid * 64 + 2 * lane]     = A[0];
                s.scratchU[1024 + wid * 64 + 2 * lane + 1] = A[1];
            }
            __syncthreads();                            // S8
            float rlu = 0.f;
            if (tid < 64) {
                #pragma unroll
                for (int k = 0; k < 16; ++k) rlu += s.scratchU[1024 + k * 64 + tid];
                st_peer(&s.rpart[tid], peer, rlu);
                arrive_peer(mbC5, peer);
            }
            mbar_wait(mbC5, par);                       // C5 (16 + 64 = 80 arrivals)
            float S = 0.f;
            #pragma unroll
            for (int k = 0; k < 8; ++k) {
                float4 v4 = ((const float4*)s.redB)[k];
                S += (v4.x + v4.y) + (v4.z + v4.w);
            }
            float invS = __fdividef(1.f, S);
            wr = wp * invS;
            if (tid < 64) s.rv[tid] = (rlu + s.rpart[tid]) * invS;
        }
        __syncthreads();                                // S9
    }

    // ---- epilogue: output t = 63 ----
    if (tid < 64) {
        int gf = tid & 7, spf = tid >> 3;
        float4 acc = make_float4(0.f, 0.f, 0.f, 0.f);
        #pragma unroll
        for (int j = 0; j < 8; ++j) {
            float v = s.rv[spf * 8 + j];
            float4 w4 = Wf4[(size_t)(256 + spf * 8 + j) * 16 + rank * 8 + gf];
            acc.x = fmaf(v, w4.x, acc.x); acc.y = fmaf(v, w4.y, acc.y);
            acc.z = fmaf(v, w4.z, acc.z); acc.w = fmaf(v, w4.w, acc.w);
        }
        *(float4*)(s.scratchF + 1024 + spf * 32 + 4 * gf) = acc;
    }
    __syncthreads();
    if (tid < 32) {
        int o = rank * 32 + tid;
        float acc = s.bfs[o] + s.fcl[o] + s.fcp[1][o];
        #pragma unroll
        for (int k = 0; k < 8; ++k) acc += s.scratchF[1024 + k * 32 + tid];
        out[((size_t)b * Tt + 63) * 64 + o] = sigmoidf_(acc);
    }
    CSYNC();   // no CTA exits while peer may still push
}

extern "C" void kernel_launch(void* const* d_in, const int* in_sizes, int n_in,
                              void* d_out, int out_size) {
    (void)in_sizes; (void)n_in; (void)out_size;
    cudaFuncSetAttribute(ntm_kernel, cudaFuncAttributeMaxDynamicSharedMemorySize,
                         (int)sizeof(Smem));
    ntm_kernel<<<128, NT, sizeof(Smem)>>>(
        (const float*)d_in[0],   // x
        (const float*)d_in[1],   // Wc
        (const float*)d_in[2],   // bc
        (const float*)d_in[3],   // Wr
        (const float*)d_in[4],   // br
        (const float*)d_in[5],   // Ww
        (const float*)d_in[6],   // bw
        (const float*)d_in[7],   // Wf
        (const float*)d_in[8],   // bf
        (const float*)d_in[9],   // r_bias
        (const float*)d_in[10],  // w_bias
        (const float*)d_in[11],  // M_bias
        (float*)d_out);
}